// round 15
// baseline (speedup 1.0000x reference)
#include <cuda_runtime.h>
#include <cuda_bf16.h>
#include <cstdint>

#define N_SEG 50000
#define D_FEAT 128
#define OUT_F 128
#define KDIM 256
#define KW    (KDIM / 2)   // 128 packed bf16x2 words per row

// Scratch (allocation-free rule: __device__ globals)
// W fragments: [plane(2)][ka(16)][n8(16)][lane(32)][reg(2)] uint32 = 128 KB
__device__ uint32_t g_wfrag[2 * 16 * 16 * 32 * 2];
__device__ int      g_starts[N_SEG + 1];
__device__ int      g_is64;

#define WFI(p, ka, n8, ln) (((((p) * 16 + (ka)) * 16 + (n8)) * 32 + (ln)) * 2)
#define AFI(p, ka, mt, ln, rg) ((((((p) * 16 + (ka)) * 8 + (mt)) * 32 + (ln)) * 4) + (rg))
#define AF_WORDS (2 * 16 * 8 * 32 * 4)   // 16384 words = 64 KB

// Split x into bf16 hi + bf16 lo (x ~= hi + lo), pack pairs along k.
__device__ __forceinline__ void split_pack(float x, float y,
                                           uint32_t& hi, uint32_t& lo) {
    __nv_bfloat162 h2 = __floats2bfloat162_rn(x, y);
    float hx = __bfloat162float(__low2bfloat16(h2));
    float hy = __bfloat162float(__high2bfloat16(h2));
    __nv_bfloat162 l2 = __floats2bfloat162_rn(x - hx, y - hy);
    hi = *(uint32_t*)&h2;
    lo = *(uint32_t*)&l2;
}

__device__ __forceinline__ void mma_bf16(float* c, const uint4& a,
                                         uint32_t b0, uint32_t b1) {
    asm volatile(
        "mma.sync.aligned.m16n8k16.row.col.f32.bf16.bf16.f32 "
        "{%0,%1,%2,%3}, {%4,%5,%6,%7}, {%8,%9}, {%0,%1,%2,%3};"
        : "+f"(c[0]), "+f"(c[1]), "+f"(c[2]), "+f"(c[3])
        : "r"(a.x), "r"(a.y), "r"(a.z), "r"(a.w), "r"(b0), "r"(b1));
}

// ---------------------------------------------------------------------------
// Kernel -1: detect whether ids are int64 or int32.
// ---------------------------------------------------------------------------
__global__ void detect_kernel(const int* __restrict__ ids32, int M) {
    int base = (M / 2) & ~1;
    int nonzero = 0;
    for (int i = 1; i <= 63; i += 2) {
        if (base + i < M) nonzero |= ids32[base + i];
    }
    g_is64 = (nonzero == 0) ? 1 : 0;
}

// ---------------------------------------------------------------------------
// Kernel 0: segment boundaries from sorted ids.
// ---------------------------------------------------------------------------
__global__ void bounds_kernel(const int* __restrict__ ids32, int M, int Nseg) {
    int m = blockIdx.x * blockDim.x + threadIdx.x;
    if (m >= M) return;
    const long long* ids64 = (const long long*)ids32;
    int is64 = g_is64;

    long long id = is64 ? ids64[m] : (long long)ids32[m];
    if (id < 0 || id >= Nseg) return;
    if (m == 0) {
        g_starts[id] = 0;
    } else {
        long long prev = is64 ? ids64[m - 1] : (long long)ids32[m - 1];
        if (prev != id) g_starts[id] = m;
    }
    if (m == M - 1) g_starts[Nseg] = M;
}

// ---------------------------------------------------------------------------
// Kernel 0b: pre-split W into bf16 hi/lo MMA B-fragments (one-time, tiny).
// m16n8k16 B-frag mapping: lane = (n&7)*4 + (kpair&3), reg = kpair>>2.
// ---------------------------------------------------------------------------
__global__ void wsplit_kernel(const float* __restrict__ W) {
    int idx = blockIdx.x * blockDim.x + threadIdx.x;   // (oo, kw) word index
    if (idx >= OUT_F * KW) return;
    int oo = idx >> 7;          // out feature 0..127
    int kw = idx & (KW - 1);    // packed k-pair 0..127
    float x = W[(size_t)oo * KDIM + 2 * kw];
    float y = W[(size_t)oo * KDIM + 2 * kw + 1];
    uint32_t hi, lo;
    split_pack(x, y, hi, lo);

    int ka = kw >> 3, kp = kw & 7;
    int n8 = oo >> 3;
    int ln = ((oo & 7) << 2) | (kp & 3);
    int rg = kp >> 2;
    g_wfrag[WFI(0, ka, n8, ln) + rg] = hi;
    g_wfrag[WFI(1, ka, n8, ln) + rg] = lo;
}

// ---------------------------------------------------------------------------
// FUSED kernel: pool 128 segments -> bf16-split fragments in smem -> MMA
// -> bias + relu -> out.  256 threads; 8 warps.
// Phase 1: warp w pools segments (row0 + 16w .. +16w+15), 32 lanes x float4,
//          scatters packed bf16x2 hi/lo into fragment-major smem.
// Phase 2: warps as 2m x 4n; per warp 4 m16-tiles x 4 n8-tiles, K=16 atoms,
//          3-term split MMA; A frag = LDS.128, B frag = LDG.64 (L2-resident).
// ---------------------------------------------------------------------------
__global__ __launch_bounds__(256, 2) void fused_kernel(const float* __restrict__ lane_enc,
                                                       const float* __restrict__ bias,
                                                       float* __restrict__ out,
                                                       int M, int Nrows) {
    extern __shared__ uint32_t sAf[];   // AF_WORDS = 64 KB

    int tid  = threadIdx.x;
    int wid  = tid >> 5;
    int lid  = tid & 31;
    int row0 = blockIdx.x * 128;

    // ---------------- Phase 1: pooling + fragment scatter ----------------
    for (int i = 0; i < 16; i++) {
        int r   = wid * 16 + i;        // local row 0..127
        int seg = row0 + r;

        float4 mx, sm;
        int valid = (seg < Nrows);
        int n = 0;
        if (valid) {
            int s = g_starts[seg];
            int e = g_starts[seg + 1];
            if (s < 0) s = 0;
            if (e > M) e = M;
            n = e - s;

            const float4* p = (const float4*)(lane_enc + (size_t)s * D_FEAT) + lid;
            float ninf = -__int_as_float(0x7f800000);
            mx = make_float4(ninf, ninf, ninf, ninf);
            sm = make_float4(0.f, 0.f, 0.f, 0.f);

            int rr = 0;
            for (; rr + 4 <= n; rr += 4) {
                float4 a0 = p[(rr + 0) * 32];
                float4 a1 = p[(rr + 1) * 32];
                float4 a2 = p[(rr + 2) * 32];
                float4 a3 = p[(rr + 3) * 32];
                mx.x = fmaxf(mx.x, fmaxf(fmaxf(a0.x, a1.x), fmaxf(a2.x, a3.x)));
                mx.y = fmaxf(mx.y, fmaxf(fmaxf(a0.y, a1.y), fmaxf(a2.y, a3.y)));
                mx.z = fmaxf(mx.z, fmaxf(fmaxf(a0.z, a1.z), fmaxf(a2.z, a3.z)));
                mx.w = fmaxf(mx.w, fmaxf(fmaxf(a0.w, a1.w), fmaxf(a2.w, a3.w)));
                sm.x += (a0.x + a1.x) + (a2.x + a3.x);
                sm.y += (a0.y + a1.y) + (a2.y + a3.y);
                sm.z += (a0.z + a1.z) + (a2.z + a3.z);
                sm.w += (a0.w + a1.w) + (a2.w + a3.w);
            }
            for (; rr < n; rr++) {
                float4 a = p[rr * 32];
                mx.x = fmaxf(mx.x, a.x); mx.y = fmaxf(mx.y, a.y);
                mx.z = fmaxf(mx.z, a.z); mx.w = fmaxf(mx.w, a.w);
                sm.x += a.x; sm.y += a.y; sm.z += a.z; sm.w += a.w;
            }
        }
        if (!valid || n <= 0) {
            mx = make_float4(0.f, 0.f, 0.f, 0.f);
            sm = make_float4(0.f, 0.f, 0.f, 0.f);
            n = 1;
        }
        float inv = 1.f / (float)n;

        // This lane owns packed words: kw = 2*lid, 2*lid+1 (max part) and
        // kw = 64 + 2*lid, 64 + 2*lid + 1 (mean part).
        int mt = r >> 4;
        int rb = ((r & 7) << 2);
        int rhi = (r >> 3) & 1;

        uint32_t hi, lo;
        #pragma unroll
        for (int q = 0; q < 4; q++) {
            int kw;
            if (q == 0)      { kw = 2 * lid;          split_pack(mx.x, mx.y, hi, lo); }
            else if (q == 1) { kw = 2 * lid + 1;      split_pack(mx.z, mx.w, hi, lo); }
            else if (q == 2) { kw = 64 + 2 * lid;     split_pack(sm.x * inv, sm.y * inv, hi, lo); }
            else             { kw = 64 + 2 * lid + 1; split_pack(sm.z * inv, sm.w * inv, hi, lo); }
            int ka = kw >> 3, kp = kw & 7;
            int ln = rb | (kp & 3);
            int rg = rhi | ((kp >> 2) << 1);
            sAf[AFI(0, ka, mt, ln, rg)] = hi;
            sAf[AFI(1, ka, mt, ln, rg)] = lo;
        }
    }
    __syncthreads();

    // ---------------- Phase 2: MMA ----------------
    int warp_m = wid & 1;    // rows warp_m*64 .. +63  (4 m16-tiles)
    int warp_n = wid >> 1;   // cols warp_n*32 .. +31  (4 n8-tiles)
    int lr = lid >> 2;
    int lc = lid & 3;

    float acc[4][4][4];
    #pragma unroll
    for (int a = 0; a < 4; a++)
        #pragma unroll
        for (int b = 0; b < 4; b++)
            #pragma unroll
            for (int c = 0; c < 4; c++) acc[a][b][c] = 0.f;

    for (int ka = 0; ka < 16; ka++) {
        uint4 ah[4], al[4];
        #pragma unroll
        for (int mt = 0; mt < 4; mt++) {
            int m8 = warp_m * 4 + mt;
            ah[mt] = *(const uint4*)&sAf[AFI(0, ka, m8, lid, 0)];
            al[mt] = *(const uint4*)&sAf[AFI(1, ka, m8, lid, 0)];
        }
        #pragma unroll
        for (int nt = 0; nt < 4; nt++) {
            int n8 = warp_n * 4 + nt;
            uint2 bh = *(const uint2*)&g_wfrag[WFI(0, ka, n8, lid)];
            uint2 bl = *(const uint2*)&g_wfrag[WFI(1, ka, n8, lid)];
            #pragma unroll
            for (int mt = 0; mt < 4; mt++) {
                mma_bf16(acc[mt][nt], ah[mt], bl.x, bl.y);  // hi*lo
                mma_bf16(acc[mt][nt], al[mt], bh.x, bh.y);  // lo*hi
                mma_bf16(acc[mt][nt], ah[mt], bh.x, bh.y);  // hi*hi
            }
        }
    }

    // ---------------- Epilogue: bias + relu ----------------
    #pragma unroll
    for (int nt = 0; nt < 4; nt++) {
        int gn = warp_n * 32 + nt * 8 + lc * 2;
        float b0 = bias[gn], b1 = bias[gn + 1];
        #pragma unroll
        for (int mt = 0; mt < 4; mt++) {
            int gm0 = row0 + warp_m * 64 + mt * 16 + lr;
            int gm1 = gm0 + 8;
            if (gm0 < Nrows) {
                float2 v;
                v.x = fmaxf(acc[mt][nt][0] + b0, 0.f);
                v.y = fmaxf(acc[mt][nt][1] + b1, 0.f);
                *(float2*)&out[(size_t)gm0 * OUT_F + gn] = v;
            }
            if (gm1 < Nrows) {
                float2 v;
                v.x = fmaxf(acc[mt][nt][2] + b0, 0.f);
                v.y = fmaxf(acc[mt][nt][3] + b1, 0.f);
                *(float2*)&out[(size_t)gm1 * OUT_F + gn] = v;
            }
        }
    }
}

extern "C" void kernel_launch(void* const* d_in, const int* in_sizes, int n_in,
                              void* d_out, int out_size) {
    const float* lane = nullptr;
    const int*   ids  = nullptr;
    const float* W    = nullptr;
    const float* bb   = nullptr;
    int M = 800000, Nseg = 50000;

    for (int i = 0; i < n_in; i++) {
        int sz = in_sizes[i];
        if (sz == 102400000)      lane = (const float*)d_in[i];
        else if (sz == 800000)  { ids  = (const int*)d_in[i]; M = sz; }
        else if (sz == 32768)     W    = (const float*)d_in[i];
        else if (sz == 128)       bb   = (const float*)d_in[i];
        else if (sz == 6400000)   Nseg = sz / D_FEAT;
    }
    if (!lane) lane = (const float*)d_in[1];
    if (!ids)  ids  = (const int*)d_in[2];
    if (!W)    W    = (const float*)d_in[3];
    if (!bb)   bb   = (const float*)d_in[4];

    float* out = (float*)d_out;

    static bool attr_done = false;
    if (!attr_done) {
        cudaFuncSetAttribute(fused_kernel,
                             cudaFuncAttributeMaxDynamicSharedMemorySize,
                             AF_WORDS * 4);
        attr_done = true;
    }

    detect_kernel<<<1, 1>>>(ids, M);
    bounds_kernel<<<(M + 255) / 256, 256>>>(ids, M, Nseg);
    wsplit_kernel<<<(OUT_F * KW + 255) / 256, 256>>>(W);
    fused_kernel<<<(Nseg + 127) / 128, 256, AF_WORDS * 4>>>(lane, bb, out, M, Nseg);
}